// round 1
// baseline (speedup 1.0000x reference)
#include <cuda_runtime.h>

#define N_NODES 10000
#define N_EDGES 320000
#define DIM_IN  128
#define DIM_H   256
#define DIM_C   32
#define DIM_OUT 64
#define CAP     256
#define MASKW   313   // ceil(10000/32)

// ---------------- scratch (device globals; no allocation allowed) -------------
__device__ unsigned g_mask[N_NODES * MASKW];       // ~12.5 MB dedup bitmask
__device__ int      g_cnt [N_NODES];
__device__ int      g_adj [N_NODES * CAP];         // deduped neighbor lists
__device__ float    g_combined[(size_t)N_NODES * 2 * DIM_H]; // [h | comm]
__device__ float    g_qk  [N_NODES * 64];          // q (0:32) | k (32:64)
__device__ float    g_v   [(size_t)N_NODES * DIM_H];
__device__ float    g_t   [(size_t)N_NODES * DIM_H];
__device__ float    g_wqk [DIM_H * 64];
__device__ float    g_bqk [64];

// ---------------- adjacency build --------------------------------------------
__global__ void clear_kernel() {
    int i = blockIdx.x * blockDim.x + threadIdx.x;
    if (i < N_NODES * MASKW) g_mask[i] = 0u;
    if (i < N_NODES) g_cnt[i] = 0;
}

__global__ void insert_kernel(const int* __restrict__ ei) {
    int e = blockIdx.x * blockDim.x + threadIdx.x;
    if (e >= N_EDGES) return;
    int i = ei[e];
    int j = ei[N_EDGES + e];
    unsigned bit = 1u << (j & 31);
    unsigned old = atomicOr(&g_mask[i * MASKW + (j >> 5)], bit);
    if (!(old & bit)) {
        int pos = atomicAdd(&g_cnt[i], 1);
        if (pos < CAP) g_adj[i * CAP + pos] = j;
    }
}

// ---------------- fuse Wq|Wk into one [256,64] B matrix -----------------------
__global__ void prep_wqk(const float* __restrict__ Wq, const float* __restrict__ bq,
                         const float* __restrict__ Wk, const float* __restrict__ bk) {
    int i = blockIdx.x * blockDim.x + threadIdx.x;
    if (i < DIM_H * 64) {
        int r = i >> 6, c = i & 63;
        g_wqk[i] = (c < 32) ? Wq[r * 32 + c] : Wk[r * 32 + (c - 32)];
    }
    if (i < 64) g_bqk[i] = (i < 32) ? bq[i] : bk[i - 32];
}

// ---------------- tiled fp32 GEMM: C = A@B + bias (opt relu) ------------------
// BM=BN=64, BK=16, 256 threads, 4x4 micro-tile per thread.
__global__ void __launch_bounds__(256)
gemm_kernel(const float* __restrict__ A, int lda,
            const float* __restrict__ B, int ldb,
            const float* __restrict__ bias,
            float* __restrict__ C, int ldc,
            int M, int Nc, int K, int relu)
{
    __shared__ __align__(16) float As[16][64];
    __shared__ __align__(16) float Bs[16][64];

    int tid = threadIdx.x;
    int m0 = blockIdx.y * 64, n0 = blockIdx.x * 64;
    int am = tid >> 2, ak = (tid & 3) * 4;      // A loader: row am, 4 k's
    int bk = tid >> 4, bn = (tid & 15) * 4;     // B loader: row bk, 4 n's
    int tx = tid & 15, ty = tid >> 4;

    float acc[4][4] = {};

    for (int k0 = 0; k0 < K; k0 += 16) {
        float4 av = make_float4(0.f, 0.f, 0.f, 0.f);
        if (m0 + am < M)
            av = *(const float4*)(A + (size_t)(m0 + am) * lda + k0 + ak);
        As[ak + 0][am] = av.x; As[ak + 1][am] = av.y;
        As[ak + 2][am] = av.z; As[ak + 3][am] = av.w;

        float4 bv = make_float4(0.f, 0.f, 0.f, 0.f);
        if (n0 + bn < Nc)
            bv = *(const float4*)(B + (size_t)(k0 + bk) * ldb + n0 + bn);
        *(float4*)&Bs[bk][bn] = bv;

        __syncthreads();
        #pragma unroll
        for (int kk = 0; kk < 16; kk++) {
            float4 a = *(const float4*)&As[kk][ty * 4];
            float4 b = *(const float4*)&Bs[kk][tx * 4];
            float ar[4] = {a.x, a.y, a.z, a.w};
            float br[4] = {b.x, b.y, b.z, b.w};
            #pragma unroll
            for (int i = 0; i < 4; i++)
                #pragma unroll
                for (int j = 0; j < 4; j++)
                    acc[i][j] += ar[i] * br[j];
        }
        __syncthreads();
    }

    #pragma unroll
    for (int i = 0; i < 4; i++) {
        int row = m0 + ty * 4 + i;
        if (row >= M) continue;
        #pragma unroll
        for (int j = 0; j < 4; j++) {
            int col = n0 + tx * 4 + j;
            if (col >= Nc) continue;
            float val = acc[i][j] + bias[col];
            if (relu) val = fmaxf(val, 0.f);
            C[(size_t)row * ldc + col] = val;
        }
    }
}

// ---------------- sparse softmax attention ------------------------------------
__device__ __forceinline__ float warpMax(float v) {
    #pragma unroll
    for (int o = 16; o > 0; o >>= 1) v = fmaxf(v, __shfl_xor_sync(0xffffffffu, v, o));
    return v;
}
__device__ __forceinline__ float warpSum(float v) {
    #pragma unroll
    for (int o = 16; o > 0; o >>= 1) v += __shfl_xor_sync(0xffffffffu, v, o);
    return v;
}

__global__ void __launch_bounds__(256) attn_kernel() {
    int row = blockIdx.x;
    int tid = threadIdx.x;

    __shared__ float s_w[CAP];
    __shared__ int   s_j[CAP];
    __shared__ float s_q[DIM_C];
    __shared__ float red[8];

    int cnt = g_cnt[row];
    if (cnt > CAP) cnt = CAP;
    if (tid < DIM_C) s_q[tid] = g_qk[row * 64 + tid];
    __syncthreads();

    float sc = -1e30f;
    if (tid < cnt) {
        int j = g_adj[row * CAP + tid];
        s_j[tid] = j;
        const float* kp = g_qk + j * 64 + 32;
        float s = 0.f;
        #pragma unroll
        for (int c = 0; c < DIM_C; c++) s += s_q[c] * kp[c];
        sc = s * 0.17677669529663687f;   // 1/sqrt(32)
    }

    // block max
    float m = warpMax(sc);
    if ((tid & 31) == 0) red[tid >> 5] = m;
    __syncthreads();
    if (tid < 32) {
        float t = (tid < 8) ? red[tid] : -1e30f;
        t = warpMax(t);
        if (tid == 0) red[0] = t;
    }
    __syncthreads();
    m = red[0];
    __syncthreads();

    float e = (tid < cnt) ? __expf(sc - m) : 0.f;
    float s1 = warpSum(e);
    if ((tid & 31) == 0) red[tid >> 5] = s1;
    __syncthreads();
    if (tid < 32) {
        float t = (tid < 8) ? red[tid] : 0.f;
        t = warpSum(t);
        if (tid == 0) red[0] = t;
    }
    __syncthreads();
    float sum = red[0];

    if (tid < cnt) s_w[tid] = e / sum;
    __syncthreads();

    // comm[row][tid] = sum_t w_t * v[j_t][tid]  (coalesced v gather, L2-resident)
    float acc = 0.f;
    #pragma unroll 4
    for (int t = 0; t < cnt; t++)
        acc += s_w[t] * g_v[(size_t)s_j[t] * DIM_H + tid];
    g_combined[(size_t)row * (2 * DIM_H) + DIM_H + tid] = acc;
}

// ---------------- launch ------------------------------------------------------
extern "C" void kernel_launch(void* const* d_in, const int* in_sizes, int n_in,
                              void* d_out, int out_size) {
    const float* x    = (const float*)d_in[0];
    const int*   ei   = (const int*)  d_in[1];
    const float* W_in = (const float*)d_in[2];
    const float* b_in = (const float*)d_in[3];
    const float* Wq   = (const float*)d_in[4];
    const float* bq   = (const float*)d_in[5];
    const float* Wk   = (const float*)d_in[6];
    const float* bk   = (const float*)d_in[7];
    const float* Wv   = (const float*)d_in[8];
    const float* bv   = (const float*)d_in[9];
    const float* W1   = (const float*)d_in[10];
    const float* b1   = (const float*)d_in[11];
    const float* W2   = (const float*)d_in[12];
    const float* b2   = (const float*)d_in[13];
    float* out = (float*)d_out;

    float *combined, *qk, *vbuf, *tbuf, *wqk, *bqk;
    cudaGetSymbolAddress((void**)&combined, g_combined);
    cudaGetSymbolAddress((void**)&qk,       g_qk);
    cudaGetSymbolAddress((void**)&vbuf,     g_v);
    cudaGetSymbolAddress((void**)&tbuf,     g_t);
    cudaGetSymbolAddress((void**)&wqk,      g_wqk);
    cudaGetSymbolAddress((void**)&bqk,      g_bqk);

    const int MG = (N_NODES + 63) / 64;   // 157

    clear_kernel <<< (N_NODES * MASKW + 255) / 256, 256 >>> ();
    insert_kernel<<< (N_EDGES + 255) / 256, 256 >>> (ei);
    prep_wqk     <<< (DIM_H * 64 + 255) / 256, 256 >>> (Wq, bq, Wk, bk);

    // h = x @ W_in + b_in  -> combined[:, :256]
    gemm_kernel<<< dim3(4, MG), 256 >>>(x, DIM_IN, W_in, DIM_H, b_in,
                                        combined, 2 * DIM_H,
                                        N_NODES, DIM_H, DIM_IN, 0);
    // [q|k] = h @ [Wq|Wk] + [bq|bk]
    gemm_kernel<<< dim3(1, MG), 256 >>>(combined, 2 * DIM_H, wqk, 64, bqk,
                                        qk, 64,
                                        N_NODES, 64, DIM_H, 0);
    // v = h @ Wv + bv
    gemm_kernel<<< dim3(4, MG), 256 >>>(combined, 2 * DIM_H, Wv, DIM_H, bv,
                                        vbuf, DIM_H,
                                        N_NODES, DIM_H, DIM_H, 0);
    // sparse softmax attention -> combined[:, 256:]
    attn_kernel<<< N_NODES, 256 >>>();
    // t = relu(combined @ W1 + b1)
    gemm_kernel<<< dim3(4, MG), 256 >>>(combined, 2 * DIM_H, W1, DIM_H, b1,
                                        tbuf, DIM_H,
                                        N_NODES, DIM_H, 2 * DIM_H, 1);
    // out = t @ W2 + b2
    gemm_kernel<<< dim3(1, MG), 256 >>>(tbuf, DIM_H, W2, DIM_OUT, b2,
                                        out, DIM_OUT,
                                        N_NODES, DIM_OUT, DIM_H, 0);
}

// round 2
// speedup vs baseline: 1.7097x; 1.7097x over previous
#include <cuda_runtime.h>
#include <cstdint>

#define N_NODES 10000
#define N_EDGES 320000
#define DIM_IN  128
#define DIM_H   256
#define DIM_C   32
#define DIM_OUT 64
#define CAP     128
#define BMPW    313   // ceil(10000/32)

// ---------------- scratch (device globals) ------------------------------------
__device__ int   g_cnt[N_NODES];
__device__ int   g_adj[N_NODES * CAP];
__device__ float g_combined[(size_t)N_NODES * 2 * DIM_H]; // [h | comm]
__device__ float g_qk [N_NODES * 64];                      // q | k
__device__ float g_v  [(size_t)N_NODES * DIM_H];
__device__ float g_t  [(size_t)N_NODES * DIM_H];
__device__ float g_wqk[DIM_H * 64];
__device__ float g_bqk[64];

// ---------------- prep: zero counts + fuse Wq|Wk -------------------------------
__global__ void prep_kernel(const float* __restrict__ Wq, const float* __restrict__ bq,
                            const float* __restrict__ Wk, const float* __restrict__ bk) {
    int i = blockIdx.x * blockDim.x + threadIdx.x;
    if (i < N_NODES) g_cnt[i] = 0;
    if (i < DIM_H * 64) {
        int r = i >> 6, c = i & 63;
        g_wqk[i] = (c < 32) ? Wq[r * 32 + c] : Wk[r * 32 + (c - 32)];
    }
    if (i < 64) g_bqk[i] = (i < 32) ? bq[i] : bk[i - 32];
}

// ---------------- adjacency: append (duplicates allowed) -----------------------
__global__ void insert_kernel(const int* __restrict__ ei) {
    int e = blockIdx.x * blockDim.x + threadIdx.x;
    if (e >= N_EDGES) return;
    int i = ei[e];
    int j = ei[N_EDGES + e];
    int pos = atomicAdd(&g_cnt[i], 1);
    if (pos < CAP) g_adj[i * CAP + pos] = j;
}

// ---------------- TF32 tensor-core GEMM ----------------------------------------
// C[M,N] = A[M,K] @ B[K,N] + bias (opt relu). BM=128 BN=64 BK=16.
// 128 threads = 4 warps (2x2), warp tile 64x32, mma.m16n8k8 tf32.
#define BM 128
#define BN 64
#define BK 16
#define ASTR 20   // As row stride (words): 20r mod 32 -> conflict-free frag reads
#define BSTR 72   // Bs row stride (words): (72k+n) mod 32 = 8k+n -> conflict-free

__device__ __forceinline__ uint32_t f2tf(float f) {
    uint32_t r;
    asm("cvt.rna.tf32.f32 %0, %1;" : "=r"(r) : "f"(f));
    return r;
}

__device__ __forceinline__ void mma_tf32(float* d, const uint32_t* a, const uint32_t* b) {
    asm("mma.sync.aligned.m16n8k8.row.col.f32.tf32.tf32.f32 "
        "{%0,%1,%2,%3}, {%4,%5,%6,%7}, {%8,%9}, {%0,%1,%2,%3};"
        : "+f"(d[0]), "+f"(d[1]), "+f"(d[2]), "+f"(d[3])
        : "r"(a[0]), "r"(a[1]), "r"(a[2]), "r"(a[3]), "r"(b[0]), "r"(b[1]));
}

__global__ void __launch_bounds__(128)
gemm_tf32(const float* __restrict__ A, int lda,
          const float* __restrict__ B, int ldb,
          const float* __restrict__ bias,
          float* __restrict__ C, int ldc,
          int M, int K, int relu)
{
    __shared__ uint32_t As[2][BM * ASTR];
    __shared__ uint32_t Bs[2][BK * BSTR];

    const int tid  = threadIdx.x;
    const int lane = tid & 31;
    const int wid  = tid >> 5;
    const int wm   = wid & 1;        // 2 warps along M (64 rows each)
    const int wn   = wid >> 1;       // 2 warps along N (32 cols each)
    const int m0   = blockIdx.y * BM;
    const int n0   = blockIdx.x * BN;

    const int ar = tid >> 2;         // A loader: row within 32-row pass
    const int ak = (tid & 3) * 4;    // A loader: k quad

    float acc[4][4][4];
    #pragma unroll
    for (int i = 0; i < 4; i++)
        #pragma unroll
        for (int j = 0; j < 4; j++)
            #pragma unroll
            for (int r = 0; r < 4; r++) acc[i][j][r] = 0.f;

    float4 la[4], lb[2];
    const int kt = K / BK;

    // ---- load tile 0
    #pragma unroll
    for (int p = 0; p < 4; p++) {
        int row = m0 + p * 32 + ar;
        la[p] = (row < M) ? *(const float4*)(A + (size_t)row * lda + ak)
                          : make_float4(0.f, 0.f, 0.f, 0.f);
    }
    #pragma unroll
    for (int p = 0; p < 2; p++) {
        int idx = p * 128 + tid;
        lb[p] = *(const float4*)(B + (size_t)(idx >> 4) * ldb + n0 + (idx & 15) * 4);
    }
    #pragma unroll
    for (int p = 0; p < 4; p++) {
        uint4 w = make_uint4(f2tf(la[p].x), f2tf(la[p].y), f2tf(la[p].z), f2tf(la[p].w));
        *(uint4*)&As[0][(p * 32 + ar) * ASTR + ak] = w;
    }
    #pragma unroll
    for (int p = 0; p < 2; p++) {
        int idx = p * 128 + tid;
        uint4 w = make_uint4(f2tf(lb[p].x), f2tf(lb[p].y), f2tf(lb[p].z), f2tf(lb[p].w));
        *(uint4*)&Bs[0][(idx >> 4) * BSTR + (idx & 15) * 4] = w;
    }
    __syncthreads();

    int buf = 0;
    for (int t = 0; t < kt; t++) {
        // prefetch next k-tile from gmem
        if (t + 1 < kt) {
            int k0 = (t + 1) * BK;
            #pragma unroll
            for (int p = 0; p < 4; p++) {
                int row = m0 + p * 32 + ar;
                la[p] = (row < M) ? *(const float4*)(A + (size_t)row * lda + k0 + ak)
                                  : make_float4(0.f, 0.f, 0.f, 0.f);
            }
            #pragma unroll
            for (int p = 0; p < 2; p++) {
                int idx = p * 128 + tid;
                lb[p] = *(const float4*)(B + (size_t)(k0 + (idx >> 4)) * ldb + n0 + (idx & 15) * 4);
            }
        }

        // compute on current buffer
        #pragma unroll
        for (int ks = 0; ks < 2; ks++) {
            const int kb = ks * 8;
            uint32_t af[4][4];
            #pragma unroll
            for (int mi = 0; mi < 4; mi++) {
                int r = wm * 64 + mi * 16 + (lane >> 2);
                int c = kb + (lane & 3);
                af[mi][0] = As[buf][r * ASTR + c];
                af[mi][1] = As[buf][(r + 8) * ASTR + c];
                af[mi][2] = As[buf][r * ASTR + c + 4];
                af[mi][3] = As[buf][(r + 8) * ASTR + c + 4];
            }
            uint32_t bf[4][2];
            #pragma unroll
            for (int ni = 0; ni < 4; ni++) {
                int n = wn * 32 + ni * 8 + (lane >> 2);
                int k = kb + (lane & 3);
                bf[ni][0] = Bs[buf][k * BSTR + n];
                bf[ni][1] = Bs[buf][(k + 4) * BSTR + n];
            }
            #pragma unroll
            for (int mi = 0; mi < 4; mi++)
                #pragma unroll
                for (int ni = 0; ni < 4; ni++)
                    mma_tf32(acc[mi][ni], af[mi], bf[ni]);
        }

        // store prefetched tile to other buffer
        if (t + 1 < kt) {
            #pragma unroll
            for (int p = 0; p < 4; p++) {
                uint4 w = make_uint4(f2tf(la[p].x), f2tf(la[p].y), f2tf(la[p].z), f2tf(la[p].w));
                *(uint4*)&As[buf ^ 1][(p * 32 + ar) * ASTR + ak] = w;
            }
            #pragma unroll
            for (int p = 0; p < 2; p++) {
                int idx = p * 128 + tid;
                uint4 w = make_uint4(f2tf(lb[p].x), f2tf(lb[p].y), f2tf(lb[p].z), f2tf(lb[p].w));
                *(uint4*)&Bs[buf ^ 1][(idx >> 4) * BSTR + (idx & 15) * 4] = w;
            }
            __syncthreads();
            buf ^= 1;
        }
    }

    // ---- epilogue: bias (+relu), store
    #pragma unroll
    for (int mi = 0; mi < 4; mi++) {
        int r0 = m0 + wm * 64 + mi * 16 + (lane >> 2);
        #pragma unroll
        for (int ni = 0; ni < 4; ni++) {
            int col = n0 + wn * 32 + ni * 8 + (lane & 3) * 2;
            float b0 = bias[col], b1 = bias[col + 1];
            float v0 = acc[mi][ni][0] + b0, v1 = acc[mi][ni][1] + b1;
            float v2 = acc[mi][ni][2] + b0, v3 = acc[mi][ni][3] + b1;
            if (relu) {
                v0 = fmaxf(v0, 0.f); v1 = fmaxf(v1, 0.f);
                v2 = fmaxf(v2, 0.f); v3 = fmaxf(v3, 0.f);
            }
            if (r0 < M)     *(float2*)&C[(size_t)r0 * ldc + col]       = make_float2(v0, v1);
            if (r0 + 8 < M) *(float2*)&C[(size_t)(r0 + 8) * ldc + col] = make_float2(v2, v3);
        }
    }
}

// ---------------- sparse softmax attention (with shared-bitmap dedup) ----------
__device__ __forceinline__ float warpMax(float v) {
    #pragma unroll
    for (int o = 16; o > 0; o >>= 1) v = fmaxf(v, __shfl_xor_sync(0xffffffffu, v, o));
    return v;
}
__device__ __forceinline__ float warpSum(float v) {
    #pragma unroll
    for (int o = 16; o > 0; o >>= 1) v += __shfl_xor_sync(0xffffffffu, v, o);
    return v;
}

__global__ void __launch_bounds__(256) attn_kernel() {
    int row = blockIdx.x;
    int tid = threadIdx.x;

    __shared__ unsigned bmp[BMPW];
    __shared__ float s_w[CAP];
    __shared__ int   s_j[CAP];
    __shared__ float s_q[DIM_C];
    __shared__ float red[8];

    for (int i = tid; i < BMPW; i += 256) bmp[i] = 0u;
    if (tid < DIM_C) s_q[tid] = g_qk[row * 64 + tid];
    int cnt = g_cnt[row];
    if (cnt > CAP) cnt = CAP;
    __syncthreads();

    float sc = -1e30f;
    if (tid < cnt) {
        int j = g_adj[row * CAP + tid];
        s_j[tid] = j;
        unsigned bit = 1u << (j & 31);
        unsigned old = atomicOr(&bmp[j >> 5], bit);
        if (!(old & bit)) {  // first occurrence only
            const float* kp = g_qk + j * 64 + 32;
            float s = 0.f;
            #pragma unroll
            for (int c = 0; c < DIM_C; c++) s += s_q[c] * kp[c];
            sc = s * 0.17677669529663687f;   // 1/sqrt(32)
        }
    }

    // block max
    float m = warpMax(sc);
    if ((tid & 31) == 0) red[tid >> 5] = m;
    __syncthreads();
    if (tid < 32) {
        float t = (tid < 8) ? red[tid] : -1e30f;
        t = warpMax(t);
        if (tid == 0) red[0] = t;
    }
    __syncthreads();
    m = red[0];
    __syncthreads();

    float e = (tid < cnt) ? __expf(sc - m) : 0.f;   // dup entries -> exp(-inf)=0
    float s1 = warpSum(e);
    if ((tid & 31) == 0) red[tid >> 5] = s1;
    __syncthreads();
    if (tid < 32) {
        float t = (tid < 8) ? red[tid] : 0.f;
        t = warpSum(t);
        if (tid == 0) red[0] = t;
    }
    __syncthreads();
    float sum = red[0];

    if (tid < cnt) s_w[tid] = e / sum;
    __syncthreads();

    float acc = 0.f;
    #pragma unroll 4
    for (int t = 0; t < cnt; t++)
        acc += s_w[t] * g_v[(size_t)s_j[t] * DIM_H + tid];
    g_combined[(size_t)row * (2 * DIM_H) + DIM_H + tid] = acc;
}

// ---------------- launch --------------------------------------------------------
extern "C" void kernel_launch(void* const* d_in, const int* in_sizes, int n_in,
                              void* d_out, int out_size) {
    const float* x    = (const float*)d_in[0];
    const int*   ei   = (const int*)  d_in[1];
    const float* W_in = (const float*)d_in[2];
    const float* b_in = (const float*)d_in[3];
    const float* Wq   = (const float*)d_in[4];
    const float* bq   = (const float*)d_in[5];
    const float* Wk   = (const float*)d_in[6];
    const float* bk   = (const float*)d_in[7];
    const float* Wv   = (const float*)d_in[8];
    const float* bv   = (const float*)d_in[9];
    const float* W1   = (const float*)d_in[10];
    const float* b1   = (const float*)d_in[11];
    const float* W2   = (const float*)d_in[12];
    const float* b2   = (const float*)d_in[13];
    float* out = (float*)d_out;

    float *combined, *qk, *vbuf, *tbuf, *wqk, *bqk;
    cudaGetSymbolAddress((void**)&combined, g_combined);
    cudaGetSymbolAddress((void**)&qk,       g_qk);
    cudaGetSymbolAddress((void**)&vbuf,     g_v);
    cudaGetSymbolAddress((void**)&tbuf,     g_t);
    cudaGetSymbolAddress((void**)&wqk,      g_wqk);
    cudaGetSymbolAddress((void**)&bqk,      g_bqk);

    const int MG = (N_NODES + BM - 1) / BM;   // 79

    prep_kernel  <<< 64, 256 >>> (Wq, bq, Wk, bk);
    insert_kernel<<< (N_EDGES + 255) / 256, 256 >>> (ei);

    // h = x @ W_in + b_in  -> combined[:, :256]
    gemm_tf32<<< dim3(4, MG), 128 >>>(x, DIM_IN, W_in, DIM_H, b_in,
                                      combined, 2 * DIM_H, N_NODES, DIM_IN, 0);
    // [q|k] = h @ [Wq|Wk]
    gemm_tf32<<< dim3(1, MG), 128 >>>(combined, 2 * DIM_H, wqk, 64, bqk,
                                      qk, 64, N_NODES, DIM_H, 0);
    // v = h @ Wv + bv
    gemm_tf32<<< dim3(4, MG), 128 >>>(combined, 2 * DIM_H, Wv, DIM_H, bv,
                                      vbuf, DIM_H, N_NODES, DIM_H, 0);
    // sparse softmax attention -> combined[:, 256:]
    attn_kernel<<< N_NODES, 256 >>>();
    // t = relu(combined @ W1 + b1)
    gemm_tf32<<< dim3(4, MG), 128 >>>(combined, 2 * DIM_H, W1, DIM_H, b1,
                                      tbuf, DIM_H, N_NODES, 2 * DIM_H, 1);
    // out = t @ W2 + b2
    gemm_tf32<<< dim3(1, MG), 128 >>>(tbuf, DIM_H, W2, DIM_OUT, b2,
                                      out, DIM_OUT, N_NODES, DIM_H, 0);
}

// round 3
// speedup vs baseline: 1.8253x; 1.0677x over previous
#include <cuda_runtime.h>
#include <cstdint>

#define N_NODES 10000
#define N_EDGES 320000
#define DIM_IN  128
#define DIM_H   256
#define DIM_C   32
#define DIM_OUT 64
#define CAP     128
#define BMPW    313   // ceil(10000/32)
#define NQV     320   // v(256) | q(32) | k(32)

// ---------------- scratch (device globals) ------------------------------------
__device__ int   g_cnt[N_NODES];
__device__ int   g_adj[N_NODES * CAP];
__device__ float g_combined[(size_t)N_NODES * 2 * DIM_H]; // [h | comm], ld=512
__device__ float g_qv [(size_t)N_NODES * NQV];            // [v | q | k], ld=320
__device__ float g_t  [(size_t)N_NODES * DIM_H];
__device__ float g_wqkv[DIM_H * NQV];                     // [Wv | Wq | Wk]
__device__ float g_bqkv[NQV];

// ---------------- prep: zero counts + fuse Wv|Wq|Wk ----------------------------
__global__ void prep_kernel(const float* __restrict__ Wq, const float* __restrict__ bq,
                            const float* __restrict__ Wk, const float* __restrict__ bk,
                            const float* __restrict__ Wv, const float* __restrict__ bv) {
    int i = blockIdx.x * blockDim.x + threadIdx.x;
    if (i < N_NODES) g_cnt[i] = 0;
    if (i < DIM_H * NQV) {
        int r = i / NQV, c = i % NQV;
        float w;
        if (c < 256)      w = Wv[r * 256 + c];
        else if (c < 288) w = Wq[r * 32 + (c - 256)];
        else              w = Wk[r * 32 + (c - 288)];
        g_wqkv[i] = w;
    }
    if (i < NQV)
        g_bqkv[i] = (i < 256) ? bv[i] : (i < 288 ? bq[i - 256] : bk[i - 288]);
}

// ---------------- adjacency: append (dups deduped later in attn) ---------------
__global__ void insert_kernel(const int* __restrict__ ei) {
    int e = blockIdx.x * blockDim.x + threadIdx.x;
    if (e >= N_EDGES) return;
    int i = ei[e];
    int j = ei[N_EDGES + e];
    int pos = atomicAdd(&g_cnt[i], 1);
    if (pos < CAP) g_adj[i * CAP + pos] = j;
}

// ---------------- TF32 tensor-core GEMM ----------------------------------------
// C[M,N] = A[M,K] @ B[K,N] + bias (opt relu). BM=64 BN=64 BK=16.
// 128 threads = 4 warps (2x2), warp tile 32x32, mma.m16n8k8 tf32.
#define BM 64
#define BN 64
#define BK 16
#define ASTR 20   // As row stride (words): conflict-free frag reads
#define BSTR 72   // Bs row stride (words): conflict-free frag reads

__device__ __forceinline__ uint32_t f2tf(float f) {
    uint32_t r;
    asm("cvt.rna.tf32.f32 %0, %1;" : "=r"(r) : "f"(f));
    return r;
}

__device__ __forceinline__ void mma_tf32(float* d, const uint32_t* a, const uint32_t* b) {
    asm("mma.sync.aligned.m16n8k8.row.col.f32.tf32.tf32.f32 "
        "{%0,%1,%2,%3}, {%4,%5,%6,%7}, {%8,%9}, {%0,%1,%2,%3};"
        : "+f"(d[0]), "+f"(d[1]), "+f"(d[2]), "+f"(d[3])
        : "r"(a[0]), "r"(a[1]), "r"(a[2]), "r"(a[3]), "r"(b[0]), "r"(b[1]));
}

__global__ void __launch_bounds__(128, 5)
gemm_tf32(const float* __restrict__ A, int lda,
          const float* __restrict__ B, int ldb,
          const float* __restrict__ bias,
          float* __restrict__ C, int ldc,
          int M, int K, int relu)
{
    __shared__ uint32_t As[2][BM * ASTR];
    __shared__ uint32_t Bs[2][BK * BSTR];

    const int tid  = threadIdx.x;
    const int lane = tid & 31;
    const int wid  = tid >> 5;
    const int wm   = wid & 1;        // 2 warps along M (32 rows each)
    const int wn   = wid >> 1;       // 2 warps along N (32 cols each)
    const int m0   = blockIdx.y * BM;
    const int n0   = blockIdx.x * BN;

    const int ar = tid >> 2;         // A loader row (0..31), 2 passes
    const int ak = (tid & 3) * 4;    // A loader k quad

    float acc[2][4][4];
    #pragma unroll
    for (int i = 0; i < 2; i++)
        #pragma unroll
        for (int j = 0; j < 4; j++)
            #pragma unroll
            for (int r = 0; r < 4; r++) acc[i][j][r] = 0.f;

    float4 la[2], lb[2];
    const int kt = K / BK;

    // ---- load tile 0
    #pragma unroll
    for (int p = 0; p < 2; p++) {
        int row = m0 + p * 32 + ar;
        la[p] = (row < M) ? *(const float4*)(A + (size_t)row * lda + ak)
                          : make_float4(0.f, 0.f, 0.f, 0.f);
        int idx = p * 128 + tid;
        lb[p] = *(const float4*)(B + (size_t)(idx >> 4) * ldb + n0 + (idx & 15) * 4);
    }
    #pragma unroll
    for (int p = 0; p < 2; p++) {
        uint4 wa = make_uint4(f2tf(la[p].x), f2tf(la[p].y), f2tf(la[p].z), f2tf(la[p].w));
        *(uint4*)&As[0][(p * 32 + ar) * ASTR + ak] = wa;
        int idx = p * 128 + tid;
        uint4 wb = make_uint4(f2tf(lb[p].x), f2tf(lb[p].y), f2tf(lb[p].z), f2tf(lb[p].w));
        *(uint4*)&Bs[0][(idx >> 4) * BSTR + (idx & 15) * 4] = wb;
    }
    __syncthreads();

    int buf = 0;
    for (int t = 0; t < kt; t++) {
        if (t + 1 < kt) {
            int k0 = (t + 1) * BK;
            #pragma unroll
            for (int p = 0; p < 2; p++) {
                int row = m0 + p * 32 + ar;
                la[p] = (row < M) ? *(const float4*)(A + (size_t)row * lda + k0 + ak)
                                  : make_float4(0.f, 0.f, 0.f, 0.f);
                int idx = p * 128 + tid;
                lb[p] = *(const float4*)(B + (size_t)(k0 + (idx >> 4)) * ldb + n0 + (idx & 15) * 4);
            }
        }

        #pragma unroll
        for (int ks = 0; ks < 2; ks++) {
            const int kb = ks * 8;
            uint32_t af[2][4];
            #pragma unroll
            for (int mi = 0; mi < 2; mi++) {
                int r = wm * 32 + mi * 16 + (lane >> 2);
                int c = kb + (lane & 3);
                af[mi][0] = As[buf][r * ASTR + c];
                af[mi][1] = As[buf][(r + 8) * ASTR + c];
                af[mi][2] = As[buf][r * ASTR + c + 4];
                af[mi][3] = As[buf][(r + 8) * ASTR + c + 4];
            }
            uint32_t bf[4][2];
            #pragma unroll
            for (int ni = 0; ni < 4; ni++) {
                int n = wn * 32 + ni * 8 + (lane >> 2);
                int k = kb + (lane & 3);
                bf[ni][0] = Bs[buf][k * BSTR + n];
                bf[ni][1] = Bs[buf][(k + 4) * BSTR + n];
            }
            #pragma unroll
            for (int mi = 0; mi < 2; mi++)
                #pragma unroll
                for (int ni = 0; ni < 4; ni++)
                    mma_tf32(acc[mi][ni], af[mi], bf[ni]);
        }

        if (t + 1 < kt) {
            #pragma unroll
            for (int p = 0; p < 2; p++) {
                uint4 wa = make_uint4(f2tf(la[p].x), f2tf(la[p].y), f2tf(la[p].z), f2tf(la[p].w));
                *(uint4*)&As[buf ^ 1][(p * 32 + ar) * ASTR + ak] = wa;
                int idx = p * 128 + tid;
                uint4 wb = make_uint4(f2tf(lb[p].x), f2tf(lb[p].y), f2tf(lb[p].z), f2tf(lb[p].w));
                *(uint4*)&Bs[buf ^ 1][(idx >> 4) * BSTR + (idx & 15) * 4] = wb;
            }
            __syncthreads();
            buf ^= 1;
        }
    }

    // ---- epilogue: bias (+relu), store
    #pragma unroll
    for (int mi = 0; mi < 2; mi++) {
        int r0 = m0 + wm * 32 + mi * 16 + (lane >> 2);
        #pragma unroll
        for (int ni = 0; ni < 4; ni++) {
            int col = n0 + wn * 32 + ni * 8 + (lane & 3) * 2;
            float b0 = bias[col], b1 = bias[col + 1];
            float v0 = acc[mi][ni][0] + b0, v1 = acc[mi][ni][1] + b1;
            float v2 = acc[mi][ni][2] + b0, v3 = acc[mi][ni][3] + b1;
            if (relu) {
                v0 = fmaxf(v0, 0.f); v1 = fmaxf(v1, 0.f);
                v2 = fmaxf(v2, 0.f); v3 = fmaxf(v3, 0.f);
            }
            if (r0 < M)     *(float2*)&C[(size_t)r0 * ldc + col]       = make_float2(v0, v1);
            if (r0 + 8 < M) *(float2*)&C[(size_t)(r0 + 8) * ldc + col] = make_float2(v2, v3);
        }
    }
}

// ---------------- sparse softmax attention (shared-bitmap dedup) ---------------
__device__ __forceinline__ float warpMax(float v) {
    #pragma unroll
    for (int o = 16; o > 0; o >>= 1) v = fmaxf(v, __shfl_xor_sync(0xffffffffu, v, o));
    return v;
}
__device__ __forceinline__ float warpSum(float v) {
    #pragma unroll
    for (int o = 16; o > 0; o >>= 1) v += __shfl_xor_sync(0xffffffffu, v, o);
    return v;
}

__global__ void __launch_bounds__(256) attn_kernel() {
    int row = blockIdx.x;
    int tid = threadIdx.x;

    __shared__ unsigned bmp[BMPW];
    __shared__ float s_w[CAP];
    __shared__ int   s_j[CAP];
    __shared__ float s_q[DIM_C];
    __shared__ float red[8];

    for (int i = tid; i < BMPW; i += 256) bmp[i] = 0u;
    if (tid < DIM_C) s_q[tid] = g_qv[(size_t)row * NQV + 256 + tid];
    int cnt = g_cnt[row];
    if (cnt > CAP) cnt = CAP;
    __syncthreads();

    float sc = -1e30f;
    if (tid < cnt) {
        int j = g_adj[row * CAP + tid];
        s_j[tid] = j;
        unsigned bit = 1u << (j & 31);
        unsigned old = atomicOr(&bmp[j >> 5], bit);
        if (!(old & bit)) {  // first occurrence only
            const float* kp = g_qv + (size_t)j * NQV + 288;
            float s = 0.f;
            #pragma unroll
            for (int c = 0; c < DIM_C; c++) s += s_q[c] * kp[c];
            sc = s * 0.17677669529663687f;   // 1/sqrt(32)
        }
    }

    float m = warpMax(sc);
    if ((tid & 31) == 0) red[tid >> 5] = m;
    __syncthreads();
    if (tid < 32) {
        float t = (tid < 8) ? red[tid] : -1e30f;
        t = warpMax(t);
        if (tid == 0) red[0] = t;
    }
    __syncthreads();
    m = red[0];
    __syncthreads();

    float e = (tid < cnt) ? __expf(sc - m) : 0.f;   // dup entries -> exp(-inf)=0
    float s1 = warpSum(e);
    if ((tid & 31) == 0) red[tid >> 5] = s1;
    __syncthreads();
    if (tid < 32) {
        float t = (tid < 8) ? red[tid] : 0.f;
        t = warpSum(t);
        if (tid == 0) red[0] = t;
    }
    __syncthreads();
    float sum = red[0];

    if (tid < cnt) s_w[tid] = e / sum;
    __syncthreads();

    float acc = 0.f;
    #pragma unroll 4
    for (int t = 0; t < cnt; t++)
        acc += s_w[t] * g_qv[(size_t)s_j[t] * NQV + tid];   // v slice
    g_combined[(size_t)row * (2 * DIM_H) + DIM_H + tid] = acc;
}

// ---------------- launch --------------------------------------------------------
extern "C" void kernel_launch(void* const* d_in, const int* in_sizes, int n_in,
                              void* d_out, int out_size) {
    const float* x    = (const float*)d_in[0];
    const int*   ei   = (const int*)  d_in[1];
    const float* W_in = (const float*)d_in[2];
    const float* b_in = (const float*)d_in[3];
    const float* Wq   = (const float*)d_in[4];
    const float* bq   = (const float*)d_in[5];
    const float* Wk   = (const float*)d_in[6];
    const float* bk   = (const float*)d_in[7];
    const float* Wv   = (const float*)d_in[8];
    const float* bv   = (const float*)d_in[9];
    const float* W1   = (const float*)d_in[10];
    const float* b1   = (const float*)d_in[11];
    const float* W2   = (const float*)d_in[12];
    const float* b2   = (const float*)d_in[13];
    float* out = (float*)d_out;

    float *combined, *qv, *tbuf, *wqkv, *bqkv;
    cudaGetSymbolAddress((void**)&combined, g_combined);
    cudaGetSymbolAddress((void**)&qv,       g_qv);
    cudaGetSymbolAddress((void**)&tbuf,     g_t);
    cudaGetSymbolAddress((void**)&wqkv,     g_wqkv);
    cudaGetSymbolAddress((void**)&bqkv,     g_bqkv);

    const int MG = (N_NODES + BM - 1) / BM;   // 157

    prep_kernel  <<< (DIM_H * NQV + 255) / 256, 256 >>> (Wq, bq, Wk, bk, Wv, bv);
    insert_kernel<<< (N_EDGES + 255) / 256, 256 >>> (ei);

    // h = x @ W_in + b_in  -> combined[:, :256]
    gemm_tf32<<< dim3(4, MG), 128 >>>(x, DIM_IN, W_in, DIM_H, b_in,
                                      combined, 2 * DIM_H, N_NODES, DIM_IN, 0);
    // [v|q|k] = h @ [Wv|Wq|Wk] + [bv|bq|bk]   (N=320)
    gemm_tf32<<< dim3(5, MG), 128 >>>(combined, 2 * DIM_H, wqkv, NQV, bqkv,
                                      qv, NQV, N_NODES, DIM_H, 0);
    // sparse softmax attention -> combined[:, 256:]
    attn_kernel<<< N_NODES, 256 >>>();
    // t = relu(combined @ W1 + b1)
    gemm_tf32<<< dim3(4, MG), 128 >>>(combined, 2 * DIM_H, W1, DIM_H, b1,
                                      tbuf, DIM_H, N_NODES, 2 * DIM_H, 1);
    // out = t @ W2 + b2
    gemm_tf32<<< dim3(1, MG), 128 >>>(tbuf, DIM_H, W2, DIM_OUT, b2,
                                      out, DIM_OUT, N_NODES, DIM_H, 0);
}

// round 4
// speedup vs baseline: 2.6525x; 1.4532x over previous
#include <cuda_runtime.h>
#include <cuda_fp16.h>
#include <cstdint>

#define N_NODES 10000
#define N_EDGES 320000
#define DIM_IN  128
#define DIM_H   256
#define DIM_C   32
#define DIM_OUT 64
#define CAP     128
#define BMPW    313   // ceil(10000/32)
#define NQV     320   // v(256) | q(32) | k(32)

// ---------------- scratch (device globals) ------------------------------------
__device__ int    g_cnt[N_NODES];
__device__ int    g_adj[N_NODES * CAP];
__device__ __half g_x16  [(size_t)N_NODES * DIM_IN];
__device__ __half g_win16[DIM_IN * DIM_H];
__device__ __half g_wqkv16[DIM_H * NQV];                 // [Wv | Wq | Wk]
__device__ __half g_w116 [2 * DIM_H * DIM_H];
__device__ __half g_w216 [DIM_H * DIM_OUT];
__device__ __half g_comb16[(size_t)N_NODES * 2 * DIM_H]; // [h | comm], ld=512
__device__ __half g_qv16 [(size_t)N_NODES * NQV];        // [v | q | k], ld=320
__device__ __half g_t16  [(size_t)N_NODES * DIM_H];
__device__ float  g_bqkv[NQV];

// ---------------- prep: zero counts, convert x + weights to fp16 ----------------
__global__ void prep_kernel(const float* __restrict__ x,
                            const float* __restrict__ W_in,
                            const float* __restrict__ Wq, const float* __restrict__ bq,
                            const float* __restrict__ Wk, const float* __restrict__ bk,
                            const float* __restrict__ Wv, const float* __restrict__ bv,
                            const float* __restrict__ W1,
                            const float* __restrict__ W2) {
    int g = blockIdx.x * blockDim.x + threadIdx.x;
    int stride = gridDim.x * blockDim.x;
    for (int i = g; i < N_NODES * DIM_IN; i += stride) g_x16[i] = __float2half_rn(x[i]);
    for (int i = g; i < DIM_IN * DIM_H;  i += stride) g_win16[i] = __float2half_rn(W_in[i]);
    for (int i = g; i < 2 * DIM_H * DIM_H; i += stride) g_w116[i] = __float2half_rn(W1[i]);
    for (int i = g; i < DIM_H * DIM_OUT; i += stride) g_w216[i] = __float2half_rn(W2[i]);
    for (int i = g; i < DIM_H * NQV; i += stride) {
        int r = i / NQV, c = i % NQV;
        float w;
        if (c < 256)      w = Wv[r * 256 + c];
        else if (c < 288) w = Wq[r * 32 + (c - 256)];
        else              w = Wk[r * 32 + (c - 288)];
        g_wqkv16[i] = __float2half_rn(w);
    }
    for (int i = g; i < NQV; i += stride)
        g_bqkv[i] = (i < 256) ? bv[i] : (i < 288 ? bq[i - 256] : bk[i - 288]);
    for (int i = g; i < N_NODES; i += stride) g_cnt[i] = 0;
}

// ---------------- adjacency: append (dups deduped later in attn) ----------------
__global__ void insert_kernel(const int* __restrict__ ei) {
    int e = blockIdx.x * blockDim.x + threadIdx.x;
    if (e >= N_EDGES) return;
    int i = ei[e];
    int j = ei[N_EDGES + e];
    int pos = atomicAdd(&g_cnt[i], 1);
    if (pos < CAP) g_adj[i * CAP + pos] = j;
}

// ---------------- FP16 tensor-core GEMM with ldmatrix ---------------------------
// C[M,N] = A[M,K] @ B[K,N] + bias (opt relu). BM=64 BN=64 BK=32.
// 128 threads = 4 warps (2x2), warp tile 32x32, mma.m16n8k16 f16 (fp32 acc).
#define BM 64
#define BN 64
#define BK 32
#define ASTR 40   // As row stride (halves): ldmatrix phases hit all 32 banks
#define BSTR 72   // Bs row stride (halves): same

__device__ __forceinline__ void ldsm_x4(uint32_t* r, uint32_t addr) {
    asm volatile("ldmatrix.sync.aligned.m8n8.x4.shared.b16 {%0,%1,%2,%3}, [%4];"
        : "=r"(r[0]), "=r"(r[1]), "=r"(r[2]), "=r"(r[3]) : "r"(addr));
}
__device__ __forceinline__ void ldsm_x4_t(uint32_t* r, uint32_t addr) {
    asm volatile("ldmatrix.sync.aligned.m8n8.x4.trans.shared.b16 {%0,%1,%2,%3}, [%4];"
        : "=r"(r[0]), "=r"(r[1]), "=r"(r[2]), "=r"(r[3]) : "r"(addr));
}
__device__ __forceinline__ void mma_f16(float* d, const uint32_t* a, const uint32_t* b) {
    asm volatile("mma.sync.aligned.m16n8k16.row.col.f32.f16.f16.f32 "
        "{%0,%1,%2,%3}, {%4,%5,%6,%7}, {%8,%9}, {%0,%1,%2,%3};"
        : "+f"(d[0]), "+f"(d[1]), "+f"(d[2]), "+f"(d[3])
        : "r"(a[0]), "r"(a[1]), "r"(a[2]), "r"(a[3]), "r"(b[0]), "r"(b[1]));
}

template<int OUT16>
__global__ void __launch_bounds__(128, 6)
gemm_f16(const __half* __restrict__ A, int lda,
         const __half* __restrict__ B, int ldb,
         const float* __restrict__ bias,
         void* __restrict__ Cv, int ldc,
         int M, int K, int relu)
{
    __shared__ __align__(16) __half As[2][BM * ASTR];
    __shared__ __align__(16) __half Bs[2][BK * BSTR];

    const int tid  = threadIdx.x;
    const int lane = tid & 31;
    const int wid  = tid >> 5;
    const int wm   = wid & 1;        // 2 warps along M (32 rows each)
    const int wn   = wid >> 1;       // 2 warps along N (32 cols each)
    const int m0   = blockIdx.y * BM;
    const int n0   = blockIdx.x * BN;

    // gmem loader indices (2 x uint4 per thread per matrix)
    const int a_row0 = tid >> 2;             // 0..31 (pass adds +32)
    const int a_seg  = (tid & 3) * 8;        // halves
    const int b_row0 = tid >> 3;             // 0..15 (pass adds +16)
    const int b_seg  = (tid & 7) * 8;

    // ldmatrix lane addresses (halves)
    const uint32_t as_base = (uint32_t)__cvta_generic_to_shared(&As[0][0]);
    const uint32_t bs_base = (uint32_t)__cvta_generic_to_shared(&Bs[0][0]);
    const int a_lane_h = (wm * 32 + (lane & 15)) * ASTR + ((lane >> 4) * 8);
    const int g3 = lane >> 3;
    const int b_lane_h = ((g3 & 1) * 8 + (lane & 7)) * BSTR + (g3 >> 1) * 8 + wn * 32;
    const uint32_t ABUF = BM * ASTR * 2;     // bytes per A buffer
    const uint32_t BBUF = BK * BSTR * 2;

    float acc[2][4][4];
    #pragma unroll
    for (int i = 0; i < 2; i++)
        #pragma unroll
        for (int j = 0; j < 4; j++)
            #pragma unroll
            for (int r = 0; r < 4; r++) acc[i][j][r] = 0.f;

    const uint4 zero4 = make_uint4(0u, 0u, 0u, 0u);
    uint4 la[2], lb[2];
    const int kt = K / BK;

    // ---- load tile 0
    #pragma unroll
    for (int p = 0; p < 2; p++) {
        int row = m0 + p * 32 + a_row0;
        la[p] = (row < M) ? *(const uint4*)(A + (size_t)row * lda + a_seg) : zero4;
        lb[p] = *(const uint4*)(B + (size_t)(p * 16 + b_row0) * ldb + n0 + b_seg);
    }
    #pragma unroll
    for (int p = 0; p < 2; p++) {
        *(uint4*)&As[0][(p * 32 + a_row0) * ASTR + a_seg] = la[p];
        *(uint4*)&Bs[0][(p * 16 + b_row0) * BSTR + b_seg] = lb[p];
    }
    __syncthreads();

    int buf = 0;
    for (int t = 0; t < kt; t++) {
        if (t + 1 < kt) {
            int k0 = (t + 1) * BK;
            #pragma unroll
            for (int p = 0; p < 2; p++) {
                int row = m0 + p * 32 + a_row0;
                la[p] = (row < M) ? *(const uint4*)(A + (size_t)row * lda + k0 + a_seg) : zero4;
                lb[p] = *(const uint4*)(B + (size_t)(k0 + p * 16 + b_row0) * ldb + n0 + b_seg);
            }
        }

        #pragma unroll
        for (int ks = 0; ks < 2; ks++) {
            const int kb = ks * 16;
            uint32_t af[2][4], bf[8];
            #pragma unroll
            for (int mi = 0; mi < 2; mi++)
                ldsm_x4(af[mi], as_base + buf * ABUF + 2 * (a_lane_h + mi * 16 * ASTR + kb));
            #pragma unroll
            for (int nh = 0; nh < 2; nh++)
                ldsm_x4_t(&bf[nh * 4], bs_base + buf * BBUF + 2 * (b_lane_h + kb * BSTR + nh * 16));
            #pragma unroll
            for (int mi = 0; mi < 2; mi++)
                #pragma unroll
                for (int nj = 0; nj < 4; nj++)
                    mma_f16(acc[mi][nj], af[mi], &bf[nj * 2]);
        }

        if (t + 1 < kt) {
            #pragma unroll
            for (int p = 0; p < 2; p++) {
                *(uint4*)&As[buf ^ 1][(p * 32 + a_row0) * ASTR + a_seg] = la[p];
                *(uint4*)&Bs[buf ^ 1][(p * 16 + b_row0) * BSTR + b_seg] = lb[p];
            }
            __syncthreads();
            buf ^= 1;
        }
    }

    // ---- epilogue: bias (+relu), store fp16 or fp32
    #pragma unroll
    for (int mi = 0; mi < 2; mi++) {
        int r0 = m0 + wm * 32 + mi * 16 + (lane >> 2);
        #pragma unroll
        for (int nj = 0; nj < 4; nj++) {
            int col = n0 + wn * 32 + nj * 8 + (lane & 3) * 2;
            float b0 = bias[col], b1 = bias[col + 1];
            float v0 = acc[mi][nj][0] + b0, v1 = acc[mi][nj][1] + b1;
            float v2 = acc[mi][nj][2] + b0, v3 = acc[mi][nj][3] + b1;
            if (relu) {
                v0 = fmaxf(v0, 0.f); v1 = fmaxf(v1, 0.f);
                v2 = fmaxf(v2, 0.f); v3 = fmaxf(v3, 0.f);
            }
            if (OUT16) {
                __half* C = (__half*)Cv;
                if (r0 < M)     *(__half2*)&C[(size_t)r0 * ldc + col]       = __floats2half2_rn(v0, v1);
                if (r0 + 8 < M) *(__half2*)&C[(size_t)(r0 + 8) * ldc + col] = __floats2half2_rn(v2, v3);
            } else {
                float* C = (float*)Cv;
                if (r0 < M)     *(float2*)&C[(size_t)r0 * ldc + col]       = make_float2(v0, v1);
                if (r0 + 8 < M) *(float2*)&C[(size_t)(r0 + 8) * ldc + col] = make_float2(v2, v3);
            }
        }
    }
}

// ---------------- sparse softmax attention (shared-bitmap dedup) ----------------
__device__ __forceinline__ float warpMax(float v) {
    #pragma unroll
    for (int o = 16; o > 0; o >>= 1) v = fmaxf(v, __shfl_xor_sync(0xffffffffu, v, o));
    return v;
}
__device__ __forceinline__ float warpSum(float v) {
    #pragma unroll
    for (int o = 16; o > 0; o >>= 1) v += __shfl_xor_sync(0xffffffffu, v, o);
    return v;
}

__global__ void __launch_bounds__(256) attn_kernel() {
    int row = blockIdx.x;
    int tid = threadIdx.x;

    __shared__ unsigned bmp[BMPW];
    __shared__ float s_w[CAP];
    __shared__ int   s_j[CAP];
    __shared__ float s_q[DIM_C];
    __shared__ float red[8];

    for (int i = tid; i < BMPW; i += 256) bmp[i] = 0u;
    if (tid < DIM_C) s_q[tid] = __half2float(g_qv16[(size_t)row * NQV + 256 + tid]);
    int cnt = g_cnt[row];
    if (cnt > CAP) cnt = CAP;
    __syncthreads();

    float sc = -1e30f;
    if (tid < cnt) {
        int j = g_adj[row * CAP + tid];
        s_j[tid] = j;
        unsigned bit = 1u << (j & 31);
        unsigned old = atomicOr(&bmp[j >> 5], bit);
        if (!(old & bit)) {  // first occurrence only
            const __half2* kp = (const __half2*)(g_qv16 + (size_t)j * NQV + 288);
            float s = 0.f;
            #pragma unroll
            for (int c = 0; c < DIM_C / 2; c++) {
                float2 f = __half22float2(kp[c]);
                s += s_q[2 * c] * f.x + s_q[2 * c + 1] * f.y;
            }
            sc = s * 0.17677669529663687f;   // 1/sqrt(32)
        }
    }

    float m = warpMax(sc);
    if ((tid & 31) == 0) red[tid >> 5] = m;
    __syncthreads();
    if (tid < 32) {
        float t = (tid < 8) ? red[tid] : -1e30f;
        t = warpMax(t);
        if (tid == 0) red[0] = t;
    }
    __syncthreads();
    m = red[0];
    __syncthreads();

    float e = (tid < cnt) ? __expf(sc - m) : 0.f;   // dup entries -> exp(-inf)=0
    float s1 = warpSum(e);
    if ((tid & 31) == 0) red[tid >> 5] = s1;
    __syncthreads();
    if (tid < 32) {
        float t = (tid < 8) ? red[tid] : 0.f;
        t = warpSum(t);
        if (tid == 0) red[0] = t;
    }
    __syncthreads();
    float sum = red[0];

    if (tid < cnt) s_w[tid] = e / sum;
    __syncthreads();

    float acc = 0.f;
    #pragma unroll 4
    for (int t = 0; t < cnt; t++)
        acc += s_w[t] * __half2float(g_qv16[(size_t)s_j[t] * NQV + tid]);  // v slice
    g_comb16[(size_t)row * (2 * DIM_H) + DIM_H + tid] = __float2half_rn(acc);
}

// ---------------- launch ----------------------------------------------------------
extern "C" void kernel_launch(void* const* d_in, const int* in_sizes, int n_in,
                              void* d_out, int out_size) {
    const float* x    = (const float*)d_in[0];
    const int*   ei   = (const int*)  d_in[1];
    const float* W_in = (const float*)d_in[2];
    const float* b_in = (const float*)d_in[3];
    const float* Wq   = (const float*)d_in[4];
    const float* bq   = (const float*)d_in[5];
    const float* Wk   = (const float*)d_in[6];
    const float* bk   = (const float*)d_in[7];
    const float* Wv   = (const float*)d_in[8];
    const float* bv   = (const float*)d_in[9];
    const float* W1   = (const float*)d_in[10];
    const float* b1   = (const float*)d_in[11];
    const float* W2   = (const float*)d_in[12];
    const float* b2   = (const float*)d_in[13];
    float* out = (float*)d_out;

    __half *x16, *win16, *wqkv16, *w116, *w216, *comb16, *qv16, *t16;
    float *bqkv;
    cudaGetSymbolAddress((void**)&x16,    g_x16);
    cudaGetSymbolAddress((void**)&win16,  g_win16);
    cudaGetSymbolAddress((void**)&wqkv16, g_wqkv16);
    cudaGetSymbolAddress((void**)&w116,   g_w116);
    cudaGetSymbolAddress((void**)&w216,   g_w216);
    cudaGetSymbolAddress((void**)&comb16, g_comb16);
    cudaGetSymbolAddress((void**)&qv16,   g_qv16);
    cudaGetSymbolAddress((void**)&t16,    g_t16);
    cudaGetSymbolAddress((void**)&bqkv,   g_bqkv);

    const int MG = (N_NODES + BM - 1) / BM;   // 157

    prep_kernel  <<< 640, 256 >>> (x, W_in, Wq, bq, Wk, bk, Wv, bv, W1, W2);
    insert_kernel<<< (N_EDGES + 255) / 256, 256 >>> (ei);

    // h = x @ W_in + b_in  -> comb16[:, :256]
    gemm_f16<1><<< dim3(4, MG), 128 >>>(x16, DIM_IN, win16, DIM_H, b_in,
                                        comb16, 2 * DIM_H, N_NODES, DIM_IN, 0);
    // [v|q|k] = h @ [Wv|Wq|Wk] + [bv|bq|bk]   (N=320)
    gemm_f16<1><<< dim3(5, MG), 128 >>>(comb16, 2 * DIM_H, wqkv16, NQV, bqkv,
                                        qv16, NQV, N_NODES, DIM_H, 0);
    // sparse softmax attention -> comb16[:, 256:]
    attn_kernel<<< N_NODES, 256 >>>();
    // t = relu(combined @ W1 + b1)
    gemm_f16<1><<< dim3(4, MG), 128 >>>(comb16, 2 * DIM_H, w116, DIM_H, b1,
                                        t16, DIM_H, N_NODES, 2 * DIM_H, 1);
    // out = t @ W2 + b2  (fp32 out)
    gemm_f16<0><<< dim3(1, MG), 128 >>>(t16, DIM_H, w216, DIM_OUT, b2,
                                        out, DIM_OUT, N_NODES, DIM_H, 0);
}

// round 5
// speedup vs baseline: 2.6590x; 1.0025x over previous
#include <cuda_runtime.h>
#include <cuda_fp16.h>
#include <cstdint>

#define N_NODES 10000
#define N_EDGES 320000
#define DIM_IN  128
#define DIM_H   256
#define DIM_C   32
#define DIM_OUT 64
#define CAP     128
#define BMPW    313   // ceil(10000/32)
#define NQV     320   // v(256) | q(32) | k(32)

// ---------------- scratch (device globals) ------------------------------------
__device__ int    g_cnt[N_NODES];
__device__ int    g_adj[N_NODES * CAP];
__device__ __half g_x16  [(size_t)N_NODES * DIM_IN];
__device__ __half g_win16[DIM_IN * DIM_H];
__device__ __half g_wqkv16[DIM_H * NQV];                 // [Wv | Wq | Wk]
__device__ __half g_w116 [2 * DIM_H * DIM_H];
__device__ __half g_w216 [DIM_H * DIM_OUT];
__device__ __half g_comb16[(size_t)N_NODES * 2 * DIM_H]; // [h | comm], ld=512
__device__ __half g_qv16 [(size_t)N_NODES * NQV];        // [v | q | k], ld=320
__device__ __half g_t16  [(size_t)N_NODES * DIM_H];
__device__ float  g_bqkv[NQV];

// ---------------- prep: zero counts, convert x + weights to fp16 ----------------
__global__ void prep_kernel(const float* __restrict__ x,
                            const float* __restrict__ W_in,
                            const float* __restrict__ Wq, const float* __restrict__ bq,
                            const float* __restrict__ Wk, const float* __restrict__ bk,
                            const float* __restrict__ Wv, const float* __restrict__ bv,
                            const float* __restrict__ W1,
                            const float* __restrict__ W2) {
    int g = blockIdx.x * blockDim.x + threadIdx.x;
    int stride = gridDim.x * blockDim.x;
    for (int i = g; i < N_NODES * DIM_IN; i += stride) g_x16[i] = __float2half_rn(x[i]);
    for (int i = g; i < DIM_IN * DIM_H;  i += stride) g_win16[i] = __float2half_rn(W_in[i]);
    for (int i = g; i < 2 * DIM_H * DIM_H; i += stride) g_w116[i] = __float2half_rn(W1[i]);
    for (int i = g; i < DIM_H * DIM_OUT; i += stride) g_w216[i] = __float2half_rn(W2[i]);
    for (int i = g; i < DIM_H * NQV; i += stride) {
        int r = i / NQV, c = i % NQV;
        float w;
        if (c < 256)      w = Wv[r * 256 + c];
        else if (c < 288) w = Wq[r * 32 + (c - 256)];
        else              w = Wk[r * 32 + (c - 288)];
        g_wqkv16[i] = __float2half_rn(w);
    }
    for (int i = g; i < NQV; i += stride)
        g_bqkv[i] = (i < 256) ? bv[i] : (i < 288 ? bq[i - 256] : bk[i - 288]);
    for (int i = g; i < N_NODES; i += stride) g_cnt[i] = 0;
}

// ---------------- adjacency: append (dups deduped later in attn) ----------------
__global__ void insert_kernel(const int* __restrict__ ei) {
    int e = blockIdx.x * blockDim.x + threadIdx.x;
    if (e >= N_EDGES) return;
    int i = ei[e];
    int j = ei[N_EDGES + e];
    int pos = atomicAdd(&g_cnt[i], 1);
    if (pos < CAP) g_adj[i * CAP + pos] = j;
}

// ---------------- FP16 tensor-core GEMM with ldmatrix ---------------------------
// C[M,N] = A[M,K] @ B[K,N] + bias (opt relu). BM=64 BN=64 BK=32.
// 128 threads = 4 warps (2x2), warp tile 32x32, mma.m16n8k16 f16 (fp32 acc).
#define BM 64
#define BN 64
#define BK 32
#define ASTR 40   // As row stride (halves): ldmatrix phases hit all 32 banks
#define BSTR 72   // Bs row stride (halves): same

__device__ __forceinline__ void ldsm_x4(uint32_t* r, uint32_t addr) {
    asm volatile("ldmatrix.sync.aligned.m8n8.x4.shared.b16 {%0,%1,%2,%3}, [%4];"
        : "=r"(r[0]), "=r"(r[1]), "=r"(r[2]), "=r"(r[3]) : "r"(addr));
}
__device__ __forceinline__ void ldsm_x4_t(uint32_t* r, uint32_t addr) {
    asm volatile("ldmatrix.sync.aligned.m8n8.x4.trans.shared.b16 {%0,%1,%2,%3}, [%4];"
        : "=r"(r[0]), "=r"(r[1]), "=r"(r[2]), "=r"(r[3]) : "r"(addr));
}
__device__ __forceinline__ void mma_f16(float* d, const uint32_t* a, const uint32_t* b) {
    asm volatile("mma.sync.aligned.m16n8k16.row.col.f32.f16.f16.f32 "
        "{%0,%1,%2,%3}, {%4,%5,%6,%7}, {%8,%9}, {%0,%1,%2,%3};"
        : "+f"(d[0]), "+f"(d[1]), "+f"(d[2]), "+f"(d[3])
        : "r"(a[0]), "r"(a[1]), "r"(a[2]), "r"(a[3]), "r"(b[0]), "r"(b[1]));
}

template<int OUT16>
__global__ void __launch_bounds__(128, 6)
gemm_f16(const __half* __restrict__ A, int lda,
         const __half* __restrict__ B, int ldb,
         const float* __restrict__ bias,
         void* __restrict__ Cv, int ldc,
         int M, int K, int relu)
{
    __shared__ __align__(16) __half As[2][BM * ASTR];
    __shared__ __align__(16) __half Bs[2][BK * BSTR];

    const int tid  = threadIdx.x;
    const int lane = tid & 31;
    const int wid  = tid >> 5;
    const int wm   = wid & 1;        // 2 warps along M (32 rows each)
    const int wn   = wid >> 1;       // 2 warps along N (32 cols each)
    const int m0   = blockIdx.y * BM;
    const int n0   = blockIdx.x * BN;

    // gmem loader indices (2 x uint4 per thread per matrix)
    const int a_row0 = tid >> 2;             // 0..31 (pass adds +32)
    const int a_seg  = (tid & 3) * 8;        // halves
    const int b_row0 = tid >> 3;             // 0..15 (pass adds +16)
    const int b_seg  = (tid & 7) * 8;

    // ldmatrix lane addresses (halves)
    const uint32_t as_base = (uint32_t)__cvta_generic_to_shared(&As[0][0]);
    const uint32_t bs_base = (uint32_t)__cvta_generic_to_shared(&Bs[0][0]);
    const int a_lane_h = (wm * 32 + (lane & 15)) * ASTR + ((lane >> 4) * 8);
    const int g3 = lane >> 3;
    const int b_lane_h = ((g3 & 1) * 8 + (lane & 7)) * BSTR + (g3 >> 1) * 8 + wn * 32;
    const uint32_t ABUF = BM * ASTR * 2;     // bytes per A buffer
    const uint32_t BBUF = BK * BSTR * 2;

    float acc[2][4][4];
    #pragma unroll
    for (int i = 0; i < 2; i++)
        #pragma unroll
        for (int j = 0; j < 4; j++)
            #pragma unroll
            for (int r = 0; r < 4; r++) acc[i][j][r] = 0.f;

    const uint4 zero4 = make_uint4(0u, 0u, 0u, 0u);
    uint4 la[2], lb[2];
    const int kt = K / BK;

    // ---- load tile 0
    #pragma unroll
    for (int p = 0; p < 2; p++) {
        int row = m0 + p * 32 + a_row0;
        la[p] = (row < M) ? *(const uint4*)(A + (size_t)row * lda + a_seg) : zero4;
        lb[p] = *(const uint4*)(B + (size_t)(p * 16 + b_row0) * ldb + n0 + b_seg);
    }
    #pragma unroll
    for (int p = 0; p < 2; p++) {
        *(uint4*)&As[0][(p * 32 + a_row0) * ASTR + a_seg] = la[p];
        *(uint4*)&Bs[0][(p * 16 + b_row0) * BSTR + b_seg] = lb[p];
    }
    __syncthreads();

    int buf = 0;
    for (int t = 0; t < kt; t++) {
        if (t + 1 < kt) {
            int k0 = (t + 1) * BK;
            #pragma unroll
            for (int p = 0; p < 2; p++) {
                int row = m0 + p * 32 + a_row0;
                la[p] = (row < M) ? *(const uint4*)(A + (size_t)row * lda + k0 + a_seg) : zero4;
                lb[p] = *(const uint4*)(B + (size_t)(k0 + p * 16 + b_row0) * ldb + n0 + b_seg);
            }
        }

        #pragma unroll
        for (int ks = 0; ks < 2; ks++) {
            const int kb = ks * 16;
            uint32_t af[2][4], bf[8];
            #pragma unroll
            for (int mi = 0; mi < 2; mi++)
                ldsm_x4(af[mi], as_base + buf * ABUF + 2 * (a_lane_h + mi * 16 * ASTR + kb));
            #pragma unroll
            for (int nh = 0; nh < 2; nh++)
                ldsm_x4_t(&bf[nh * 4], bs_base + buf * BBUF + 2 * (b_lane_h + kb * BSTR + nh * 16));
            #pragma unroll
            for (int mi = 0; mi < 2; mi++)
                #pragma unroll
                for (int nj = 0; nj < 4; nj++)
                    mma_f16(acc[mi][nj], af[mi], &bf[nj * 2]);
        }

        if (t + 1 < kt) {
            #pragma unroll
            for (int p = 0; p < 2; p++) {
                *(uint4*)&As[buf ^ 1][(p * 32 + a_row0) * ASTR + a_seg] = la[p];
                *(uint4*)&Bs[buf ^ 1][(p * 16 + b_row0) * BSTR + b_seg] = lb[p];
            }
            __syncthreads();
            buf ^= 1;
        }
    }

    // ---- epilogue: bias (+relu), store fp16 or fp32
    #pragma unroll
    for (int mi = 0; mi < 2; mi++) {
        int r0 = m0 + wm * 32 + mi * 16 + (lane >> 2);
        #pragma unroll
        for (int nj = 0; nj < 4; nj++) {
            int col = n0 + wn * 32 + nj * 8 + (lane & 3) * 2;
            float b0 = bias[col], b1 = bias[col + 1];
            float v0 = acc[mi][nj][0] + b0, v1 = acc[mi][nj][1] + b1;
            float v2 = acc[mi][nj][2] + b0, v3 = acc[mi][nj][3] + b1;
            if (relu) {
                v0 = fmaxf(v0, 0.f); v1 = fmaxf(v1, 0.f);
                v2 = fmaxf(v2, 0.f); v3 = fmaxf(v3, 0.f);
            }
            if (OUT16) {
                __half* C = (__half*)Cv;
                if (r0 < M)     *(__half2*)&C[(size_t)r0 * ldc + col]       = __floats2half2_rn(v0, v1);
                if (r0 + 8 < M) *(__half2*)&C[(size_t)(r0 + 8) * ldc + col] = __floats2half2_rn(v2, v3);
            } else {
                float* C = (float*)Cv;
                if (r0 < M)     *(float2*)&C[(size_t)r0 * ldc + col]       = make_float2(v0, v1);
                if (r0 + 8 < M) *(float2*)&C[(size_t)(r0 + 8) * ldc + col] = make_float2(v2, v3);
            }
        }
    }
}

// ---------------- sparse softmax attention (shared-bitmap dedup) ----------------
__device__ __forceinline__ float warpMax(float v) {
    #pragma unroll
    for (int o = 16; o > 0; o >>= 1) v = fmaxf(v, __shfl_xor_sync(0xffffffffu, v, o));
    return v;
}
__device__ __forceinline__ float warpSum(float v) {
    #pragma unroll
    for (int o = 16; o > 0; o >>= 1) v += __shfl_xor_sync(0xffffffffu, v, o);
    return v;
}

__global__ void __launch_bounds__(256) attn_kernel() {
    int row = blockIdx.x;
    int tid = threadIdx.x;

    __shared__ unsigned bmp[BMPW];
    __shared__ float s_w[CAP];
    __shared__ int   s_j[CAP];
    __shared__ float s_q[DIM_C];
    __shared__ float red[8];

    for (int i = tid; i < BMPW; i += 256) bmp[i] = 0u;
    if (tid < DIM_C) s_q[tid] = __half2float(g_qv16[(size_t)row * NQV + 256 + tid]);
    int cnt = g_cnt[row];
    if (cnt > CAP) cnt = CAP;
    __syncthreads();

    float sc = -1e30f;
    if (tid < cnt) {
        int j = g_adj[row * CAP + tid];
        s_j[tid] = j;
        unsigned bit = 1u << (j & 31);
        unsigned old = atomicOr(&bmp[j >> 5], bit);
        if (!(old & bit)) {  // first occurrence only
            const __half2* kp = (const __half2*)(g_qv16 + (size_t)j * NQV + 288);
            float s = 0.f;
            #pragma unroll
            for (int c = 0; c < DIM_C / 2; c++) {
                float2 f = __half22float2(kp[c]);
                s += s_q[2 * c] * f.x + s_q[2 * c + 1] * f.y;
            }
            sc = s * 0.17677669529663687f;   // 1/sqrt(32)
        }
    }

    float m = warpMax(sc);
    if ((tid & 31) == 0) red[tid >> 5] = m;
    __syncthreads();
    if (tid < 32) {
        float t = (tid < 8) ? red[tid] : -1e30f;
        t = warpMax(t);
        if (tid == 0) red[0] = t;
    }
    __syncthreads();
    m = red[0];
    __syncthreads();

    float e = (tid < cnt) ? __expf(sc - m) : 0.f;   // dup entries -> exp(-inf)=0
    float s1 = warpSum(e);
    if ((tid & 31) == 0) red[tid >> 5] = s1;
    __syncthreads();
    if (tid < 32) {
        float t = (tid < 8) ? red[tid] : 0.f;
        t = warpSum(t);
        if (tid == 0) red[0] = t;
    }
    __syncthreads();
    float sum = red[0];

    if (tid < cnt) s_w[tid] = e / sum;
    __syncthreads();

    float acc = 0.f;
    #pragma unroll 4
    for (int t = 0; t < cnt; t++)
        acc += s_w[t] * __half2float(g_qv16[(size_t)s_j[t] * NQV + tid]);  // v slice
    g_comb16[(size_t)row * (2 * DIM_H) + DIM_H + tid] = __float2half_rn(acc);
}

// ---------------- launch ----------------------------------------------------------
extern "C" void kernel_launch(void* const* d_in, const int* in_sizes, int n_in,
                              void* d_out, int out_size) {
    const float* x    = (const float*)d_in[0];
    const int*   ei   = (const int*)  d_in[1];
    const float* W_in = (const float*)d_in[2];
    const float* b_in = (const float*)d_in[3];
    const float* Wq   = (const float*)d_in[4];
    const float* bq   = (const float*)d_in[5];
    const float* Wk   = (const float*)d_in[6];
    const float* bk   = (const float*)d_in[7];
    const float* Wv   = (const float*)d_in[8];
    const float* bv   = (const float*)d_in[9];
    const float* W1   = (const float*)d_in[10];
    const float* b1   = (const float*)d_in[11];
    const float* W2   = (const float*)d_in[12];
    const float* b2   = (const float*)d_in[13];
    float* out = (float*)d_out;

    __half *x16, *win16, *wqkv16, *w116, *w216, *comb16, *qv16, *t16;
    float *bqkv;
    cudaGetSymbolAddress((void**)&x16,    g_x16);
    cudaGetSymbolAddress((void**)&win16,  g_win16);
    cudaGetSymbolAddress((void**)&wqkv16, g_wqkv16);
    cudaGetSymbolAddress((void**)&w116,   g_w116);
    cudaGetSymbolAddress((void**)&w216,   g_w216);
    cudaGetSymbolAddress((void**)&comb16, g_comb16);
    cudaGetSymbolAddress((void**)&qv16,   g_qv16);
    cudaGetSymbolAddress((void**)&t16,    g_t16);
    cudaGetSymbolAddress((void**)&bqkv,   g_bqkv);

    const int MG = (N_NODES + BM - 1) / BM;   // 157

    prep_kernel  <<< 640, 256 >>> (x, W_in, Wq, bq, Wk, bk, Wv, bv, W1, W2);
    insert_kernel<<< (N_EDGES + 255) / 256, 256 >>> (ei);

    // h = x @ W_in + b_in  -> comb16[:, :256]
    gemm_f16<1><<< dim3(4, MG), 128 >>>(x16, DIM_IN, win16, DIM_H, b_in,
                                        comb16, 2 * DIM_H, N_NODES, DIM_IN, 0);
    // [v|q|k] = h @ [Wv|Wq|Wk] + [bv|bq|bk]   (N=320)
    gemm_f16<1><<< dim3(5, MG), 128 >>>(comb16, 2 * DIM_H, wqkv16, NQV, bqkv,
                                        qv16, NQV, N_NODES, DIM_H, 0);
    // sparse softmax attention -> comb16[:, 256:]
    attn_kernel<<< N_NODES, 256 >>>();
    // t = relu(combined @ W1 + b1)
    gemm_f16<1><<< dim3(4, MG), 128 >>>(comb16, 2 * DIM_H, w116, DIM_H, b1,
                                        t16, DIM_H, N_NODES, 2 * DIM_H, 1);
    // out = t @ W2 + b2  (fp32 out)
    gemm_f16<0><<< dim3(1, MG), 128 >>>(t16, DIM_H, w216, DIM_OUT, b2,
                                        out, DIM_OUT, N_NODES, DIM_H, 0);
}